// round 5
// baseline (speedup 1.0000x reference)
#include <cuda_runtime.h>
#include <cuda_bf16.h>
#include <math_constants.h>

// Problem constants (fixed by the dataset)
#define ROWS 2048     // B*N = 8*256
#define D    128      // hidden
#define E    64       // edge MLP hidden
#define NJ   256      // neighbors per row
#define TR   16       // rows per block in stage-2

// Device scratch (no cudaMalloc allowed)
__device__ float g_P[ROWS * E];        // P[row][k] = h[row]·W1[0:128,k] + b1[k]
__device__ float g_agg[ROWS * 2 * D];  // per row: [agg_mean(128) | agg_max(128)]

union F2U { float2 f2; unsigned long long u; };

// Packed dual-fp32 FMA (sm_100+): acc.{lo,hi} += a.{lo,hi} * b.{lo,hi}
__device__ __forceinline__ void fma2(unsigned long long &acc,
                                     unsigned long long a,
                                     unsigned long long b) {
    asm("fma.rn.f32x2 %0, %1, %2, %0;" : "+l"(acc) : "l"(a), "l"(b));
}

// ---------------------------------------------------------------------------
// Kernel 1: P[row][k] = b1[k] + sum_d h[row][d] * W1[d][k]
// ---------------------------------------------------------------------------
__global__ void __launch_bounds__(64)
prep_kernel(const float* __restrict__ h, const float* __restrict__ W1,
            const float* __restrict__ b1) {
    const int row = blockIdx.x;
    const int t = threadIdx.x;
    __shared__ float sh[D];
    sh[t]      = h[row * D + t];
    sh[t + 64] = h[row * D + 64 + t];
    __syncthreads();
    float a0 = b1[t], a1 = 0.f, a2 = 0.f, a3 = 0.f;
#pragma unroll
    for (int d = 0; d < D; d += 4) {
        a0 = fmaf(sh[d + 0], W1[(d + 0) * E + t], a0);
        a1 = fmaf(sh[d + 1], W1[(d + 1) * E + t], a1);
        a2 = fmaf(sh[d + 2], W1[(d + 2) * E + t], a2);
        a3 = fmaf(sh[d + 3], W1[(d + 3) * E + t], a3);
    }
    g_P[row * E + t] = (a0 + a1) + (a2 + a3);
}

// ---------------------------------------------------------------------------
// Kernel 2: main gated-message kernel. One block per row (b,i), 128 threads,
// thread = output channel d. Iterates over the compacted masked-j list;
// accumulates sum/max/min of gates, then forms agg_mean/agg_max analytically.
// ---------------------------------------------------------------------------
__global__ void __launch_bounds__(128)
gate_kernel(const float* __restrict__ h, const float* __restrict__ ef,
            const unsigned int* __restrict__ adj,
            const float* __restrict__ W1, const float* __restrict__ W2,
            const float* __restrict__ b2) {
    const int row  = blockIdx.x;
    const int tid  = threadIdx.x;
    const int w    = tid >> 5;
    const int lane = tid & 31;

    __shared__ float sP[E];
    __shared__ __align__(16) float sE[NJ * 3];
    __shared__ __align__(16) float sT[2][E];
    __shared__ int sJ[NJ];
    __shared__ int sWcnt[4];

    const float hd = h[row * D + tid];

    if (tid < E) sP[tid] = g_P[row * E + tid];

    // Stage the whole edge-feature row (3 KB) into smem, coalesced.
    const float* efr = ef + (size_t)row * (NJ * 3);
#pragma unroll
    for (int i = 0; i < 6; i++) sE[tid + i * 128] = efr[tid + i * 128];

    // Deterministic, order-preserving compaction of masked j's (ballot+popc).
    // Raw nonzero test works for bool serialized as int32 (0/1) OR float32 (0.0/1.0).
    const unsigned int* adjr = adj + (size_t)row * NJ;
    const int j0 = w * 64 + lane;
    const int j1 = w * 64 + 32 + lane;
    const int m0 = (adjr[j0] != 0u);
    const int m1 = (adjr[j1] != 0u);
    const unsigned bal0 = __ballot_sync(0xffffffffu, m0);
    const unsigned bal1 = __ballot_sync(0xffffffffu, m1);
    if (lane == 0) sWcnt[w] = __popc(bal0) + __popc(bal1);
    __syncthreads();
    int base = 0;
#pragma unroll
    for (int ww = 0; ww < 4; ww++) if (ww < w) base += sWcnt[ww];
    const int cnt = sWcnt[0] + sWcnt[1] + sWcnt[2] + sWcnt[3];
    const unsigned ltm = (1u << lane) - 1u;
    if (m0) sJ[base + __popc(bal0 & ltm)] = j0;
    if (m1) sJ[base + __popc(bal0) + __popc(bal1 & ltm)] = j1;

    // Per-thread constants: edge part of W1 (for t-phase threads) and this
    // thread's W2 column, pre-packed as 32 fp32x2 pairs along k.
    float w1e0 = 0.f, w1e1 = 0.f, w1e2 = 0.f;
    if (tid < E) {
        w1e0 = W1[128 * E + tid];
        w1e1 = W1[129 * E + tid];
        w1e2 = W1[130 * E + tid];
    }
    unsigned long long w2u[32];
#pragma unroll
    for (int kk = 0; kk < 32; kk++) {
        F2U p;
        p.f2 = make_float2(W2[(2 * kk) * D + tid], W2[(2 * kk + 1) * D + tid]);
        w2u[kk] = p.u;
    }
    const float b2d = b2[tid];
    __syncthreads();

    float sumg = 0.f;
    float gmax = -CUDART_INF_F;
    float gmin =  CUDART_INF_F;

    for (int idx = 0; idx < cnt; idx++) {
        const int j = sJ[idx];
        const int p = idx & 1;   // double-buffered t: one barrier per edge
        if (tid < E) {
            const float e0 = sE[3 * j + 0];
            const float e1 = sE[3 * j + 1];
            const float e2 = sE[3 * j + 2];
            float tv = fmaf(e2, w1e2, fmaf(e1, w1e1, fmaf(e0, w1e0, sP[tid])));
            sT[p][tid] = fmaxf(tv, 0.f);
        }
        __syncthreads();

        unsigned long long acc = 0ull;  // {0.f, 0.f}
        const float4* tp = (const float4*)(&sT[p][0]);
#pragma unroll
        for (int q = 0; q < 16; q++) {
            const float4 t4 = tp[q];           // broadcast LDS.128
            F2U lo, hi;
            lo.f2 = make_float2(t4.x, t4.y);
            hi.f2 = make_float2(t4.z, t4.w);
            fma2(acc, lo.u, w2u[2 * q + 0]);
            fma2(acc, hi.u, w2u[2 * q + 1]);
        }
        F2U r; r.u = acc;
        const float z = r.f2.x + r.f2.y + b2d;
        const float g = __fdividef(1.f, 1.f + __expf(-z));
        sumg += g;
        gmax = fmaxf(gmax, g);
        gmin = fminf(gmin, g);
    }

    float cm, cx;
    if (cnt == 0) {
        cm = 0.f; cx = 0.f;   // sum=0, clip(count,1)=1; max: -inf -> 0
    } else {
        cm = hd * sumg / (float)cnt;
        cx = (hd >= 0.f) ? hd * gmax : hd * gmin;  // g>0, h const over j
    }
    g_agg[row * (2 * D) + tid]     = cm;
    g_agg[row * (2 * D) + D + tid] = cx;
}

// ---------------------------------------------------------------------------
// Kernel 3: update MLP + residual + LayerNorm. 16 rows per block so U1/U2
// global loads are reused 16x. Thread = output channel d.
// ---------------------------------------------------------------------------
__global__ void __launch_bounds__(128)
update_kernel(const float* __restrict__ h,
              const float* __restrict__ U1, const float* __restrict__ b3,
              const float* __restrict__ U2, const float* __restrict__ b4,
              const float* __restrict__ gamma, const float* __restrict__ beta,
              float* __restrict__ out) {
    const int rbase = blockIdx.x * TR;
    const int tid = threadIdx.x;
    __shared__ __align__(16) float sa[TR][3 * D];  // [h | mean | max]
    __shared__ __align__(16) float sy[TR][D];
    __shared__ float wsum[4][TR], wsq[4][TR];

    for (int idx = tid; idx < TR * 3 * D; idx += 128) {
        const int r = idx / (3 * D);
        const int m = idx % (3 * D);
        float v;
        if (m < D) v = h[(rbase + r) * D + m];
        else       v = g_agg[(rbase + r) * (2 * D) + (m - D)];
        sa[r][m] = v;
    }
    __syncthreads();

    float acc[TR];
    {
        const float bb = b3[tid];
#pragma unroll
        for (int r = 0; r < TR; r++) acc[r] = bb;
    }
    for (int g4 = 0; g4 < 96; g4++) {
        const int m = g4 * 4;
        const float u0 = U1[(m + 0) * D + tid];
        const float u1 = U1[(m + 1) * D + tid];
        const float u2 = U1[(m + 2) * D + tid];
        const float u3 = U1[(m + 3) * D + tid];
#pragma unroll
        for (int r = 0; r < TR; r++) {
            const float4 a4 = *(const float4*)(&sa[r][m]);
            acc[r] = fmaf(a4.x, u0, acc[r]);
            acc[r] = fmaf(a4.y, u1, acc[r]);
            acc[r] = fmaf(a4.z, u2, acc[r]);
            acc[r] = fmaf(a4.w, u3, acc[r]);
        }
    }
#pragma unroll
    for (int r = 0; r < TR; r++) sy[r][tid] = fmaxf(acc[r], 0.f);
    __syncthreads();

    {
        const float bb = b4[tid];
#pragma unroll
        for (int r = 0; r < TR; r++) acc[r] = bb;
    }
    for (int g4 = 0; g4 < 32; g4++) {
        const int k = g4 * 4;
        const float u0 = U2[(k + 0) * D + tid];
        const float u1 = U2[(k + 1) * D + tid];
        const float u2 = U2[(k + 2) * D + tid];
        const float u3 = U2[(k + 3) * D + tid];
#pragma unroll
        for (int r = 0; r < TR; r++) {
            const float4 y4 = *(const float4*)(&sy[r][k]);
            acc[r] = fmaf(y4.x, u0, acc[r]);
            acc[r] = fmaf(y4.y, u1, acc[r]);
            acc[r] = fmaf(y4.z, u2, acc[r]);
            acc[r] = fmaf(y4.w, u3, acc[r]);
        }
    }
    // residual: x = h + upd
#pragma unroll
    for (int r = 0; r < TR; r++) acc[r] += sa[r][tid];

    // LayerNorm over d (block-wide reduction: warp shuffles + smem combine)
    const int w = tid >> 5, lane = tid & 31;
#pragma unroll
    for (int r = 0; r < TR; r++) {
        float s = acc[r];
        float q = acc[r] * acc[r];
#pragma unroll
        for (int off = 16; off; off >>= 1) {
            s += __shfl_down_sync(0xffffffffu, s, off);
            q += __shfl_down_sync(0xffffffffu, q, off);
        }
        if (lane == 0) { wsum[w][r] = s; wsq[w][r] = q; }
    }
    __syncthreads();
    const float gm = gamma[tid];
    const float bt = beta[tid];
#pragma unroll
    for (int r = 0; r < TR; r++) {
        const float ts = wsum[0][r] + wsum[1][r] + wsum[2][r] + wsum[3][r];
        const float tq = wsq[0][r] + wsq[1][r] + wsq[2][r] + wsq[3][r];
        const float mu  = ts * (1.f / 128.f);
        const float var = tq * (1.f / 128.f) - mu * mu;
        const float inv = rsqrtf(var + 1e-5f);
        out[(rbase + r) * D + tid] = (acc[r] - mu) * inv * gm + bt;
    }
}

// ---------------------------------------------------------------------------
extern "C" void kernel_launch(void* const* d_in, const int* in_sizes, int n_in,
                              void* d_out, int out_size) {
    const float*        h     = (const float*)d_in[0];
    const float*        ef    = (const float*)d_in[1];
    const unsigned int* adj   = (const unsigned int*)d_in[2];
    const float*        W1    = (const float*)d_in[3];
    const float*        b1    = (const float*)d_in[4];
    const float*        W2    = (const float*)d_in[5];
    const float*        b2    = (const float*)d_in[6];
    const float*        U1    = (const float*)d_in[7];
    const float*        b3    = (const float*)d_in[8];
    const float*        U2    = (const float*)d_in[9];
    const float*        b4    = (const float*)d_in[10];
    const float*        gamma = (const float*)d_in[11];
    const float*        beta  = (const float*)d_in[12];
    float* out = (float*)d_out;

    prep_kernel<<<ROWS, 64>>>(h, W1, b1);
    gate_kernel<<<ROWS, 128>>>(h, ef, adj, W1, W2, b2);
    update_kernel<<<ROWS / TR, 128>>>(h, U1, b3, U2, b4, gamma, beta, out);
}

// round 9
// speedup vs baseline: 2.6332x; 2.6332x over previous
#include <cuda_runtime.h>
#include <cuda_fp16.h>
#include <math_constants.h>
#include <cstdint>

// Problem constants
#define ROWS 2048     // B*N
#define D    128
#define E    64
#define NJ   256
#define RPC  4        // rows per CTA in gate kernel
#define TR   16       // rows per block in update kernel
#define PITCH 144     // sT row pitch in bytes (128B data + 16B skew)

__device__ float g_agg[ROWS * 2 * D];   // per row: [agg_mean(128) | agg_max(128)]

__device__ __forceinline__ uint32_t pack_h2(float a, float b) {
    __half2 h = __floats2half2_rn(a, b);
    return *(uint32_t*)&h;
}

// D = A(16x16) * B(16x8) + D, fp16 in / fp32 acc. Emits HMMA.16816 on sm_103.
__device__ __forceinline__ void mma16816(float c[4], const uint32_t a[4],
                                         uint32_t b0, uint32_t b1) {
    asm volatile(
        "mma.sync.aligned.m16n8k16.row.col.f32.f16.f16.f32 "
        "{%0,%1,%2,%3}, {%4,%5,%6,%7}, {%8,%9}, {%0,%1,%2,%3};"
        : "+f"(c[0]), "+f"(c[1]), "+f"(c[2]), "+f"(c[3])
        : "r"(a[0]), "r"(a[1]), "r"(a[2]), "r"(a[3]), "r"(b0), "r"(b1));
}

// sigmoid(z + b2) given ha = 0.5*z + 0.5*b2   (1 MUFU)
__device__ __forceinline__ float sig_half(float ha) {
    float t;
    asm("tanh.approx.f32 %0, %1;" : "=f"(t) : "f"(ha));
    return fmaf(t, 0.5f, 0.5f);
}

// ---------------------------------------------------------------------------
// Gate kernel: one CTA = RPC rows, 128 threads (4 warps).
// Per row: compact masked j; build T[s][k]=relu(P[k]+e·W1e) fp16 in smem;
// per-warp mma.sync GEMM Z[d= warp's 32][j] ; thread-local sigmoid/sum/max/min
// over j; 4-lane shuffle finish; write agg_mean/agg_max.
// ---------------------------------------------------------------------------
__global__ void __launch_bounds__(128)
gate_kernel(const float* __restrict__ h, const float* __restrict__ ef,
            const unsigned int* __restrict__ adj,
            const float* __restrict__ W1, const float* __restrict__ b1,
            const float* __restrict__ W2, const float* __restrict__ b2) {
    __shared__ __align__(16) char  sT[NJ * PITCH];   // fp16 T tile, skewed rows
    __shared__ __align__(16) float sE[NJ * 4];       // edge feats, float4/row
    __shared__ float sH[RPC * D];
    __shared__ float sP[RPC * E];
    __shared__ int   sJ[NJ];
    __shared__ int   sW[4];

    const int tid  = threadIdx.x;
    const int w    = tid >> 5;
    const int lane = tid & 31;
    const int g    = lane >> 2;      // groupID
    const int t4   = lane & 3;       // thread-in-group
    const int row0 = blockIdx.x * RPC;

    // ---- A fragments: A[d][k] = W2[k][d], 2 m-tiles per warp, 4 k-steps ----
    uint32_t afr[2][4][4];
#pragma unroll
    for (int mt = 0; mt < 2; mt++) {
        const int d0 = (2 * w + mt) * 16 + g;
#pragma unroll
        for (int ks = 0; ks < 4; ks++) {
            const int k0 = ks * 16 + 2 * t4;
            afr[mt][ks][0] = pack_h2(W2[k0 * D + d0],       W2[(k0 + 1) * D + d0]);
            afr[mt][ks][1] = pack_h2(W2[k0 * D + d0 + 8],   W2[(k0 + 1) * D + d0 + 8]);
            afr[mt][ks][2] = pack_h2(W2[(k0 + 8) * D + d0], W2[(k0 + 9) * D + d0]);
            afr[mt][ks][3] = pack_h2(W2[(k0 + 8) * D + d0 + 8], W2[(k0 + 9) * D + d0 + 8]);
        }
    }
    // d-slot map: i = mt*2 + rh -> d = (2w+mt)*16 + g + rh*8
    int   dsl[4];
    float hb2[4];
#pragma unroll
    for (int i = 0; i < 4; i++) {
        const int mt = i >> 1, rh = i & 1;
        dsl[i] = (2 * w + mt) * 16 + g + rh * 8;
        hb2[i] = 0.5f * b2[dsl[i]];
    }

    // ---- stage h rows ----
    for (int idx = tid; idx < RPC * D; idx += 128)
        sH[idx] = h[(size_t)row0 * D + idx];
    __syncthreads();

    // ---- P[r][k] = b1[k] + sum_d h[r][d]*W1[d][k]  (rows rr, rr+2) ----
    {
        const int kk = tid & 63, rr = tid >> 6;
        float p0 = b1[kk], p1 = p0;
#pragma unroll 4
        for (int d = 0; d < D; d++) {
            const float wv = __ldg(&W1[d * E + kk]);
            p0 = fmaf(sH[rr * D + d],       wv, p0);
            p1 = fmaf(sH[(rr + 2) * D + d], wv, p1);
        }
        sP[rr * E + kk]       = p0;
        sP[(rr + 2) * E + kk] = p1;
    }

    // T-build per-thread constants: k-pair kp = lane (32 pairs), group q = warp
    const int kp = lane;
    const int k0 = 2 * kp;
    const float2 w1e0 = *(const float2*)(W1 + 128 * E + k0);
    const float2 w1e1 = *(const float2*)(W1 + 129 * E + k0);
    const float2 w1e2 = *(const float2*)(W1 + 130 * E + k0);
    __syncthreads();

    for (int r = 0; r < RPC; r++) {
        const int row = row0 + r;

        // edge feats -> padded smem (float4 per j)
        const float* efr = ef + (size_t)row * (NJ * 3);
#pragma unroll
        for (int i = 0; i < 6; i++) {
            const int idx = tid + i * 128;
            sE[(idx / 3) * 4 + (idx % 3)] = efr[idx];
        }

        // order-preserving mask compaction
        const unsigned int* adjr = adj + (size_t)row * NJ;
        const int j0 = w * 64 + lane, j1 = w * 64 + 32 + lane;
        const int m0 = (adjr[j0] != 0u), m1 = (adjr[j1] != 0u);
        const unsigned bal0 = __ballot_sync(0xffffffffu, m0);
        const unsigned bal1 = __ballot_sync(0xffffffffu, m1);
        if (lane == 0) sW[w] = __popc(bal0) + __popc(bal1);
        __syncthreads();
        int base = 0;
#pragma unroll
        for (int ww = 0; ww < 4; ww++) if (ww < w) base += sW[ww];
        const int cnt = sW[0] + sW[1] + sW[2] + sW[3];
        const unsigned ltm = (1u << lane) - 1u;
        if (m0) sJ[base + __popc(bal0 & ltm)] = j0;
        if (m1) sJ[base + __popc(bal0) + __popc(bal1 & ltm)] = j1;
        __syncthreads();

        if (cnt > 0) {
            // ---- T build: T[s][k] = relu(P[r][k] + e·W1e), fp16x2 per kp ----
            const float2 P2 = *(const float2*)(sP + r * E + k0);
            for (int s = w; s < cnt; s += 4) {
                const int j = sJ[s];
                const float4 e = *(const float4*)(sE + 4 * j);
                float v0 = fmaf(e.z, w1e2.x, fmaf(e.y, w1e1.x, fmaf(e.x, w1e0.x, P2.x)));
                float v1 = fmaf(e.z, w1e2.y, fmaf(e.y, w1e1.y, fmaf(e.x, w1e0.y, P2.y)));
                *(uint32_t*)(sT + s * PITCH + kp * 4) =
                    pack_h2(fmaxf(v0, 0.f), fmaxf(v1, 0.f));
            }
            __syncthreads();

            // ---- mma over j-tiles of 8 ----
            float sm[4] = {0.f, 0.f, 0.f, 0.f};
            float zx[4] = {-CUDART_INF_F, -CUDART_INF_F, -CUDART_INF_F, -CUDART_INF_F};
            float zn[4] = { CUDART_INF_F,  CUDART_INF_F,  CUDART_INF_F,  CUDART_INF_F};
            const int ntile = (cnt + 7) >> 3;
            const char* sTrow = sT + (size_t)g * PITCH;

            for (int jt = 0; jt < ntile; jt++) {
                float c0[4] = {0.f, 0.f, 0.f, 0.f};
                float c1[4] = {0.f, 0.f, 0.f, 0.f};
                const char* tb = sTrow + jt * (8 * PITCH) + t4 * 4;
#pragma unroll
                for (int ks = 0; ks < 4; ks++) {
                    const uint32_t b0 = *(const uint32_t*)(tb + ks * 32);
                    const uint32_t b1r = *(const uint32_t*)(tb + ks * 32 + 16);
                    mma16816(c0, afr[0][ks], b0, b1r);
                    mma16816(c1, afr[1][ks], b0, b1r);
                }
                const int s0 = jt * 8 + 2 * t4;
#define UPDZ(i, zz) do { const float _z = (zz); \
        sm[i] += sig_half(fmaf(_z, 0.5f, hb2[i])); \
        zx[i] = fmaxf(zx[i], _z); zn[i] = fminf(zn[i], _z); } while (0)
                if (s0 < cnt) {
                    UPDZ(0, c0[0]); UPDZ(1, c0[2]); UPDZ(2, c1[0]); UPDZ(3, c1[2]);
                }
                if (s0 + 1 < cnt) {
                    UPDZ(0, c0[1]); UPDZ(1, c0[3]); UPDZ(2, c1[1]); UPDZ(3, c1[3]);
                }
#undef UPDZ
            }

            // 4-lane (t4 group) reduction
#pragma unroll
            for (int off = 1; off <= 2; off <<= 1) {
#pragma unroll
                for (int i = 0; i < 4; i++) {
                    sm[i] += __shfl_xor_sync(0xffffffffu, sm[i], off);
                    zx[i] = fmaxf(zx[i], __shfl_xor_sync(0xffffffffu, zx[i], off));
                    zn[i] = fminf(zn[i], __shfl_xor_sync(0xffffffffu, zn[i], off));
                }
            }
            if (t4 == 0) {
                const float cntf = (float)cnt;
#pragma unroll
                for (int i = 0; i < 4; i++) {
                    const int d = dsl[i];
                    const float hd = sH[r * D + d];
                    const float cm = hd * sm[i] / cntf;
                    const float gx = sig_half(fmaf(zx[i], 0.5f, hb2[i]));
                    const float gn = sig_half(fmaf(zn[i], 0.5f, hb2[i]));
                    const float cx = (hd >= 0.f) ? hd * gx : hd * gn;
                    g_agg[(size_t)row * (2 * D) + d]     = cm;
                    g_agg[(size_t)row * (2 * D) + D + d] = cx;
                }
            }
        } else {
            g_agg[(size_t)row * (2 * D) + tid]     = 0.f;
            g_agg[(size_t)row * (2 * D) + D + tid] = 0.f;
        }
        __syncthreads();   // protect sE/sJ/sT reuse next row
    }
}

// ---------------------------------------------------------------------------
// Update MLP + residual + LayerNorm (unchanged — validated in R5)
// ---------------------------------------------------------------------------
__global__ void __launch_bounds__(128)
update_kernel(const float* __restrict__ h,
              const float* __restrict__ U1, const float* __restrict__ b3,
              const float* __restrict__ U2, const float* __restrict__ b4,
              const float* __restrict__ gamma, const float* __restrict__ beta,
              float* __restrict__ out) {
    const int rbase = blockIdx.x * TR;
    const int tid = threadIdx.x;
    __shared__ __align__(16) float sa[TR][3 * D];
    __shared__ __align__(16) float sy[TR][D];
    __shared__ float wsum[4][TR], wsq[4][TR];

    for (int idx = tid; idx < TR * 3 * D; idx += 128) {
        const int r = idx / (3 * D);
        const int m = idx % (3 * D);
        float v;
        if (m < D) v = h[(rbase + r) * D + m];
        else       v = g_agg[(size_t)(rbase + r) * (2 * D) + (m - D)];
        sa[r][m] = v;
    }
    __syncthreads();

    float acc[TR];
    {
        const float bb = b3[tid];
#pragma unroll
        for (int r = 0; r < TR; r++) acc[r] = bb;
    }
    for (int g4 = 0; g4 < 96; g4++) {
        const int m = g4 * 4;
        const float u0 = U1[(m + 0) * D + tid];
        const float u1 = U1[(m + 1) * D + tid];
        const float u2 = U1[(m + 2) * D + tid];
        const float u3 = U1[(m + 3) * D + tid];
#pragma unroll
        for (int r = 0; r < TR; r++) {
            const float4 a4 = *(const float4*)(&sa[r][m]);
            acc[r] = fmaf(a4.x, u0, acc[r]);
            acc[r] = fmaf(a4.y, u1, acc[r]);
            acc[r] = fmaf(a4.z, u2, acc[r]);
            acc[r] = fmaf(a4.w, u3, acc[r]);
        }
    }
#pragma unroll
    for (int r = 0; r < TR; r++) sy[r][tid] = fmaxf(acc[r], 0.f);
    __syncthreads();

    {
        const float bb = b4[tid];
#pragma unroll
        for (int r = 0; r < TR; r++) acc[r] = bb;
    }
    for (int g4 = 0; g4 < 32; g4++) {
        const int k = g4 * 4;
        const float u0 = U2[(k + 0) * D + tid];
        const float u1 = U2[(k + 1) * D + tid];
        const float u2 = U2[(k + 2) * D + tid];
        const float u3 = U2[(k + 3) * D + tid];
#pragma unroll
        for (int r = 0; r < TR; r++) {
            const float4 y4 = *(const float4*)(&sy[r][k]);
            acc[r] = fmaf(y4.x, u0, acc[r]);
            acc[r] = fmaf(y4.y, u1, acc[r]);
            acc[r] = fmaf(y4.z, u2, acc[r]);
            acc[r] = fmaf(y4.w, u3, acc[r]);
        }
    }
#pragma unroll
    for (int r = 0; r < TR; r++) acc[r] += sa[r][tid];

    const int w = tid >> 5, lane = tid & 31;
#pragma unroll
    for (int r = 0; r < TR; r++) {
        float s = acc[r];
        float q = acc[r] * acc[r];
#pragma unroll
        for (int off = 16; off; off >>= 1) {
            s += __shfl_down_sync(0xffffffffu, s, off);
            q += __shfl_down_sync(0xffffffffu, q, off);
        }
        if (lane == 0) { wsum[w][r] = s; wsq[w][r] = q; }
    }
    __syncthreads();
    const float gm = gamma[tid];
    const float bt = beta[tid];
#pragma unroll
    for (int r = 0; r < TR; r++) {
        const float ts = wsum[0][r] + wsum[1][r] + wsum[2][r] + wsum[3][r];
        const float tq = wsq[0][r] + wsq[1][r] + wsq[2][r] + wsq[3][r];
        const float mu  = ts * (1.f / 128.f);
        const float var = tq * (1.f / 128.f) - mu * mu;
        const float inv = rsqrtf(var + 1e-5f);
        out[(rbase + r) * D + tid] = (acc[r] - mu) * inv * gm + bt;
    }
}

// ---------------------------------------------------------------------------
extern "C" void kernel_launch(void* const* d_in, const int* in_sizes, int n_in,
                              void* d_out, int out_size) {
    const float*        h     = (const float*)d_in[0];
    const float*        ef    = (const float*)d_in[1];
    const unsigned int* adj   = (const unsigned int*)d_in[2];
    const float*        W1    = (const float*)d_in[3];
    const float*        b1    = (const float*)d_in[4];
    const float*        W2    = (const float*)d_in[5];
    const float*        b2    = (const float*)d_in[6];
    const float*        U1    = (const float*)d_in[7];
    const float*        b3    = (const float*)d_in[8];
    const float*        U2    = (const float*)d_in[9];
    const float*        b4    = (const float*)d_in[10];
    const float*        gamma = (const float*)d_in[11];
    const float*        beta  = (const float*)d_in[12];
    float* out = (float*)d_out;

    gate_kernel<<<ROWS / RPC, 128>>>(h, ef, adj, W1, b1, W2, b2);
    update_kernel<<<ROWS / TR, 128>>>(h, U1, b3, U2, b4, gamma, beta, out);
}

// round 10
// speedup vs baseline: 3.1943x; 1.2131x over previous
#include <cuda_runtime.h>
#include <cuda_fp16.h>
#include <math_constants.h>
#include <cstdint>

// Problem constants
#define ROWS 2048     // B*N
#define D    128
#define E    64
#define NJ   256
#define RPC  4        // rows per CTA in gate kernel
#define TR   8        // rows per block in update kernel (split-k, 256 thr)
#define PITCH 144     // sT row pitch in bytes (128B data + 16B skew)

__device__ float g_agg[ROWS * 2 * D];   // per row: [agg_mean(128) | agg_max(128)]

__device__ __forceinline__ uint32_t pack_h2(float a, float b) {
    __half2 h = __floats2half2_rn(a, b);
    return *(uint32_t*)&h;
}

// D = A(16x16) * B(16x8) + D, fp16 in / fp32 acc. Emits HMMA.16816 on sm_103.
__device__ __forceinline__ void mma16816(float c[4], const uint32_t a[4],
                                         uint32_t b0, uint32_t b1) {
    asm volatile(
        "mma.sync.aligned.m16n8k16.row.col.f32.f16.f16.f32 "
        "{%0,%1,%2,%3}, {%4,%5,%6,%7}, {%8,%9}, {%0,%1,%2,%3};"
        : "+f"(c[0]), "+f"(c[1]), "+f"(c[2]), "+f"(c[3])
        : "r"(a[0]), "r"(a[1]), "r"(a[2]), "r"(a[3]), "r"(b0), "r"(b1));
}

// sigmoid(z + b2) given ha = 0.5*z + 0.5*b2   (1 MUFU)
__device__ __forceinline__ float sig_half(float ha) {
    float t;
    asm("tanh.approx.f32 %0, %1;" : "=f"(t) : "f"(ha));
    return fmaf(t, 0.5f, 0.5f);
}

// ---------------------------------------------------------------------------
// Gate kernel (unchanged from R9 — validated, ~10us). One CTA = RPC rows.
// ---------------------------------------------------------------------------
__global__ void __launch_bounds__(128)
gate_kernel(const float* __restrict__ h, const float* __restrict__ ef,
            const unsigned int* __restrict__ adj,
            const float* __restrict__ W1, const float* __restrict__ b1,
            const float* __restrict__ W2, const float* __restrict__ b2) {
    __shared__ __align__(16) char  sT[NJ * PITCH];   // fp16 T tile, skewed rows
    __shared__ __align__(16) float sE[NJ * 4];       // edge feats, float4/row
    __shared__ float sH[RPC * D];
    __shared__ float sP[RPC * E];
    __shared__ int   sJ[NJ];
    __shared__ int   sW[4];

    const int tid  = threadIdx.x;
    const int w    = tid >> 5;
    const int lane = tid & 31;
    const int g    = lane >> 2;      // groupID
    const int t4   = lane & 3;       // thread-in-group
    const int row0 = blockIdx.x * RPC;

    // ---- A fragments: A[d][k] = W2[k][d], 2 m-tiles per warp, 4 k-steps ----
    uint32_t afr[2][4][4];
#pragma unroll
    for (int mt = 0; mt < 2; mt++) {
        const int d0 = (2 * w + mt) * 16 + g;
#pragma unroll
        for (int ks = 0; ks < 4; ks++) {
            const int k0 = ks * 16 + 2 * t4;
            afr[mt][ks][0] = pack_h2(W2[k0 * D + d0],       W2[(k0 + 1) * D + d0]);
            afr[mt][ks][1] = pack_h2(W2[k0 * D + d0 + 8],   W2[(k0 + 1) * D + d0 + 8]);
            afr[mt][ks][2] = pack_h2(W2[(k0 + 8) * D + d0], W2[(k0 + 9) * D + d0]);
            afr[mt][ks][3] = pack_h2(W2[(k0 + 8) * D + d0 + 8], W2[(k0 + 9) * D + d0 + 8]);
        }
    }
    // d-slot map: i = mt*2 + rh -> d = (2w+mt)*16 + g + rh*8
    int   dsl[4];
    float hb2[4];
#pragma unroll
    for (int i = 0; i < 4; i++) {
        const int mt = i >> 1, rh = i & 1;
        dsl[i] = (2 * w + mt) * 16 + g + rh * 8;
        hb2[i] = 0.5f * b2[dsl[i]];
    }

    // ---- stage h rows ----
    for (int idx = tid; idx < RPC * D; idx += 128)
        sH[idx] = h[(size_t)row0 * D + idx];
    __syncthreads();

    // ---- P[r][k] = b1[k] + sum_d h[r][d]*W1[d][k]  (rows rr, rr+2) ----
    {
        const int kk = tid & 63, rr = tid >> 6;
        float p0 = b1[kk], p1 = p0;
#pragma unroll 4
        for (int d = 0; d < D; d++) {
            const float wv = __ldg(&W1[d * E + kk]);
            p0 = fmaf(sH[rr * D + d],       wv, p0);
            p1 = fmaf(sH[(rr + 2) * D + d], wv, p1);
        }
        sP[rr * E + kk]       = p0;
        sP[(rr + 2) * E + kk] = p1;
    }

    // T-build per-thread constants
    const int kp = lane;
    const int k0 = 2 * kp;
    const float2 w1e0 = *(const float2*)(W1 + 128 * E + k0);
    const float2 w1e1 = *(const float2*)(W1 + 129 * E + k0);
    const float2 w1e2 = *(const float2*)(W1 + 130 * E + k0);
    __syncthreads();

    for (int r = 0; r < RPC; r++) {
        const int row = row0 + r;

        // edge feats -> padded smem (float4 per j)
        const float* efr = ef + (size_t)row * (NJ * 3);
#pragma unroll
        for (int i = 0; i < 6; i++) {
            const int idx = tid + i * 128;
            sE[(idx / 3) * 4 + (idx % 3)] = efr[idx];
        }

        // order-preserving mask compaction
        const unsigned int* adjr = adj + (size_t)row * NJ;
        const int j0 = w * 64 + lane, j1 = w * 64 + 32 + lane;
        const int m0 = (adjr[j0] != 0u), m1 = (adjr[j1] != 0u);
        const unsigned bal0 = __ballot_sync(0xffffffffu, m0);
        const unsigned bal1 = __ballot_sync(0xffffffffu, m1);
        if (lane == 0) sW[w] = __popc(bal0) + __popc(bal1);
        __syncthreads();
        int base = 0;
#pragma unroll
        for (int ww = 0; ww < 4; ww++) if (ww < w) base += sW[ww];
        const int cnt = sW[0] + sW[1] + sW[2] + sW[3];
        const unsigned ltm = (1u << lane) - 1u;
        if (m0) sJ[base + __popc(bal0 & ltm)] = j0;
        if (m1) sJ[base + __popc(bal0) + __popc(bal1 & ltm)] = j1;
        __syncthreads();

        if (cnt > 0) {
            // ---- T build: T[s][k] = relu(P[r][k] + e·W1e), fp16x2 per kp ----
            const float2 P2 = *(const float2*)(sP + r * E + k0);
            for (int s = w; s < cnt; s += 4) {
                const int j = sJ[s];
                const float4 e = *(const float4*)(sE + 4 * j);
                float v0 = fmaf(e.z, w1e2.x, fmaf(e.y, w1e1.x, fmaf(e.x, w1e0.x, P2.x)));
                float v1 = fmaf(e.z, w1e2.y, fmaf(e.y, w1e1.y, fmaf(e.x, w1e0.y, P2.y)));
                *(uint32_t*)(sT + s * PITCH + kp * 4) =
                    pack_h2(fmaxf(v0, 0.f), fmaxf(v1, 0.f));
            }
            __syncthreads();

            // ---- mma over j-tiles of 8 ----
            float sm[4] = {0.f, 0.f, 0.f, 0.f};
            float zx[4] = {-CUDART_INF_F, -CUDART_INF_F, -CUDART_INF_F, -CUDART_INF_F};
            float zn[4] = { CUDART_INF_F,  CUDART_INF_F,  CUDART_INF_F,  CUDART_INF_F};
            const int ntile = (cnt + 7) >> 3;
            const char* sTrow = sT + (size_t)g * PITCH;

            for (int jt = 0; jt < ntile; jt++) {
                float c0[4] = {0.f, 0.f, 0.f, 0.f};
                float c1[4] = {0.f, 0.f, 0.f, 0.f};
                const char* tb = sTrow + jt * (8 * PITCH) + t4 * 4;
#pragma unroll
                for (int ks = 0; ks < 4; ks++) {
                    const uint32_t b0 = *(const uint32_t*)(tb + ks * 32);
                    const uint32_t b1r = *(const uint32_t*)(tb + ks * 32 + 16);
                    mma16816(c0, afr[0][ks], b0, b1r);
                    mma16816(c1, afr[1][ks], b0, b1r);
                }
                const int s0 = jt * 8 + 2 * t4;
#define UPDZ(i, zz) do { const float _z = (zz); \
        sm[i] += sig_half(fmaf(_z, 0.5f, hb2[i])); \
        zx[i] = fmaxf(zx[i], _z); zn[i] = fminf(zn[i], _z); } while (0)
                if (s0 < cnt) {
                    UPDZ(0, c0[0]); UPDZ(1, c0[2]); UPDZ(2, c1[0]); UPDZ(3, c1[2]);
                }
                if (s0 + 1 < cnt) {
                    UPDZ(0, c0[1]); UPDZ(1, c0[3]); UPDZ(2, c1[1]); UPDZ(3, c1[3]);
                }
#undef UPDZ
            }

            // 4-lane (t4 group) reduction
#pragma unroll
            for (int off = 1; off <= 2; off <<= 1) {
#pragma unroll
                for (int i = 0; i < 4; i++) {
                    sm[i] += __shfl_xor_sync(0xffffffffu, sm[i], off);
                    zx[i] = fmaxf(zx[i], __shfl_xor_sync(0xffffffffu, zx[i], off));
                    zn[i] = fminf(zn[i], __shfl_xor_sync(0xffffffffu, zn[i], off));
                }
            }
            if (t4 == 0) {
                const float cntf = (float)cnt;
#pragma unroll
                for (int i = 0; i < 4; i++) {
                    const int d = dsl[i];
                    const float hd = sH[r * D + d];
                    const float cm = hd * sm[i] / cntf;
                    const float gx = sig_half(fmaf(zx[i], 0.5f, hb2[i]));
                    const float gn = sig_half(fmaf(zn[i], 0.5f, hb2[i]));
                    const float cx = (hd >= 0.f) ? hd * gx : hd * gn;
                    g_agg[(size_t)row * (2 * D) + d]     = cm;
                    g_agg[(size_t)row * (2 * D) + D + d] = cx;
                }
            }
        } else {
            g_agg[(size_t)row * (2 * D) + tid]     = 0.f;
            g_agg[(size_t)row * (2 * D) + D + tid] = 0.f;
        }
        __syncthreads();   // protect sE/sJ/sT reuse next row
    }
}

// ---------------------------------------------------------------------------
// Update MLP + residual + LayerNorm — restructured for parallelism:
// 256 blocks x 256 threads, TR=8 rows/block, 2-way split-k per GEMM.
// thread = (d = tid&127, half = tid>>7). Partials combine in smem.
// LN finish: warp w owns row w (8 warps = 8 rows), pure shuffle reduction.
// ---------------------------------------------------------------------------
__global__ void __launch_bounds__(256)
update_kernel(const float* __restrict__ h,
              const float* __restrict__ U1, const float* __restrict__ b3,
              const float* __restrict__ U2, const float* __restrict__ b4,
              const float* __restrict__ gamma, const float* __restrict__ beta,
              float* __restrict__ out) {
    const int rbase = blockIdx.x * TR;
    const int tid  = threadIdx.x;
    const int d    = tid & 127;
    const int half = tid >> 7;
    __shared__ __align__(16) float sa[TR][3 * D];     // [h | mean | max]  12KB
    __shared__ __align__(16) float sy[TR][D];         // relu hidden        4KB
    __shared__ __align__(16) float sacc[2][TR][D];    // split-k partials   8KB

    // stage input rows
    for (int idx = tid; idx < TR * 3 * D; idx += 256) {
        const int r = idx / (3 * D);
        const int m = idx % (3 * D);
        float v;
        if (m < D) v = h[(rbase + r) * D + m];
        else       v = g_agg[(size_t)(rbase + r) * (2 * D) + (m - D)];
        sa[r][m] = v;
    }
    __syncthreads();

    float acc[TR];
    // ---- GEMM1: y = relu(X @ U1 + b3), k-half = 192 per thread ----
    {
        const float init = half ? 0.f : b3[d];
#pragma unroll
        for (int r = 0; r < TR; r++) acc[r] = init;
    }
    const int m0 = half * 192;
    for (int g4 = 0; g4 < 48; g4++) {
        const int m = m0 + g4 * 4;
        const float u0 = U1[(m + 0) * D + d];
        const float u1 = U1[(m + 1) * D + d];
        const float u2 = U1[(m + 2) * D + d];
        const float u3 = U1[(m + 3) * D + d];
#pragma unroll
        for (int r = 0; r < TR; r++) {
            const float4 a4 = *(const float4*)(&sa[r][m]);
            acc[r] = fmaf(a4.x, u0, acc[r]);
            acc[r] = fmaf(a4.y, u1, acc[r]);
            acc[r] = fmaf(a4.z, u2, acc[r]);
            acc[r] = fmaf(a4.w, u3, acc[r]);
        }
    }
#pragma unroll
    for (int r = 0; r < TR; r++) sacc[half][r][d] = acc[r];
    __syncthreads();

    // combine + relu
    for (int idx = tid; idx < TR * D; idx += 256) {
        const int r = idx >> 7, dd = idx & 127;
        sy[r][dd] = fmaxf(sacc[0][r][dd] + sacc[1][r][dd], 0.f);
    }
    __syncthreads();

    // ---- GEMM2: upd = y @ U2 + b4, k-half = 64 per thread ----
    {
        const float init = half ? 0.f : b4[d];
#pragma unroll
        for (int r = 0; r < TR; r++) acc[r] = init;
    }
    const int kk0 = half * 64;
    for (int g4 = 0; g4 < 16; g4++) {
        const int k = kk0 + g4 * 4;
        const float u0 = U2[(k + 0) * D + d];
        const float u1 = U2[(k + 1) * D + d];
        const float u2 = U2[(k + 2) * D + d];
        const float u3 = U2[(k + 3) * D + d];
#pragma unroll
        for (int r = 0; r < TR; r++) {
            const float4 y4 = *(const float4*)(&sy[r][k]);
            acc[r] = fmaf(y4.x, u0, acc[r]);
            acc[r] = fmaf(y4.y, u1, acc[r]);
            acc[r] = fmaf(y4.z, u2, acc[r]);
            acc[r] = fmaf(y4.w, u3, acc[r]);
        }
    }
#pragma unroll
    for (int r = 0; r < TR; r++) sacc[half][r][d] = acc[r];
    __syncthreads();

    // ---- residual + LayerNorm: warp w owns row w ----
    const int w = tid >> 5, lane = tid & 31;
    float x[4];
    float s = 0.f, q = 0.f;
#pragma unroll
    for (int i = 0; i < 4; i++) {
        const int dd = lane + i * 32;
        x[i] = sa[w][dd] + sacc[0][w][dd] + sacc[1][w][dd];
        s += x[i];
        q = fmaf(x[i], x[i], q);
    }
#pragma unroll
    for (int off = 16; off; off >>= 1) {
        s += __shfl_xor_sync(0xffffffffu, s, off);
        q += __shfl_xor_sync(0xffffffffu, q, off);
    }
    const float mu  = s * (1.f / 128.f);
    const float var = q * (1.f / 128.f) - mu * mu;
    const float inv = rsqrtf(var + 1e-5f);
#pragma unroll
    for (int i = 0; i < 4; i++) {
        const int dd = lane + i * 32;
        out[(rbase + w) * D + dd] = (x[i] - mu) * inv * gamma[dd] + beta[dd];
    }
}

// ---------------------------------------------------------------------------
extern "C" void kernel_launch(void* const* d_in, const int* in_sizes, int n_in,
                              void* d_out, int out_size) {
    const float*        h     = (const float*)d_in[0];
    const float*        ef    = (const float*)d_in[1];
    const unsigned int* adj   = (const unsigned int*)d_in[2];
    const float*        W1    = (const float*)d_in[3];
    const float*        b1    = (const float*)d_in[4];
    const float*        W2    = (const float*)d_in[5];
    const float*        b2    = (const float*)d_in[6];
    const float*        U1    = (const float*)d_in[7];
    const float*        b3    = (const float*)d_in[8];
    const float*        U2    = (const float*)d_in[9];
    const float*        b4    = (const float*)d_in[10];
    const float*        gamma = (const float*)d_in[11];
    const float*        beta  = (const float*)d_in[12];
    float* out = (float*)d_out;

    gate_kernel<<<ROWS / RPC, 128>>>(h, ef, adj, W1, b1, W2, b2);
    update_kernel<<<ROWS / TR, 256>>>(h, U1, b3, U2, b4, gamma, beta, out);
}

// round 11
// speedup vs baseline: 3.2343x; 1.0125x over previous
#include <cuda_runtime.h>
#include <cuda_fp16.h>
#include <math_constants.h>
#include <cstdint>

// Problem constants
#define ROWS 2048     // B*N
#define D    128
#define E    64
#define NJ   256
#define RPC  4        // rows per CTA in gate kernel
#define TR   4        // rows per block in update kernel (4-way split-k, 512 thr)
#define PITCH 144     // sT row pitch in bytes (128B data + 16B skew)

__device__ float g_agg[ROWS * 2 * D];   // per row: [agg_mean(128) | agg_max(128)]

__device__ __forceinline__ uint32_t pack_h2(float a, float b) {
    __half2 h = __floats2half2_rn(a, b);
    return *(uint32_t*)&h;
}

// D = A(16x16) * B(16x8) + D, fp16 in / fp32 acc. Emits HMMA.16816 on sm_103.
__device__ __forceinline__ void mma16816(float c[4], const uint32_t a[4],
                                         uint32_t b0, uint32_t b1) {
    asm volatile(
        "mma.sync.aligned.m16n8k16.row.col.f32.f16.f16.f32 "
        "{%0,%1,%2,%3}, {%4,%5,%6,%7}, {%8,%9}, {%0,%1,%2,%3};"
        : "+f"(c[0]), "+f"(c[1]), "+f"(c[2]), "+f"(c[3])
        : "r"(a[0]), "r"(a[1]), "r"(a[2]), "r"(a[3]), "r"(b0), "r"(b1));
}

// sigmoid(z + b2) given ha = 0.5*z + 0.5*b2   (1 MUFU)
__device__ __forceinline__ float sig_half(float ha) {
    float t;
    asm("tanh.approx.f32 %0, %1;" : "=f"(t) : "f"(ha));
    return fmaf(t, 0.5f, 0.5f);
}

// ---------------------------------------------------------------------------
// Gate kernel (unchanged from R9 — validated). One CTA = RPC rows.
// ---------------------------------------------------------------------------
__global__ void __launch_bounds__(128)
gate_kernel(const float* __restrict__ h, const float* __restrict__ ef,
            const unsigned int* __restrict__ adj,
            const float* __restrict__ W1, const float* __restrict__ b1,
            const float* __restrict__ W2, const float* __restrict__ b2) {
    __shared__ __align__(16) char  sT[NJ * PITCH];   // fp16 T tile, skewed rows
    __shared__ __align__(16) float sE[NJ * 4];       // edge feats, float4/row
    __shared__ float sH[RPC * D];
    __shared__ float sP[RPC * E];
    __shared__ int   sJ[NJ];
    __shared__ int   sW[4];

    const int tid  = threadIdx.x;
    const int w    = tid >> 5;
    const int lane = tid & 31;
    const int g    = lane >> 2;      // groupID
    const int t4   = lane & 3;       // thread-in-group
    const int row0 = blockIdx.x * RPC;

    // ---- A fragments: A[d][k] = W2[k][d], 2 m-tiles per warp, 4 k-steps ----
    uint32_t afr[2][4][4];
#pragma unroll
    for (int mt = 0; mt < 2; mt++) {
        const int d0 = (2 * w + mt) * 16 + g;
#pragma unroll
        for (int ks = 0; ks < 4; ks++) {
            const int k0 = ks * 16 + 2 * t4;
            afr[mt][ks][0] = pack_h2(W2[k0 * D + d0],       W2[(k0 + 1) * D + d0]);
            afr[mt][ks][1] = pack_h2(W2[k0 * D + d0 + 8],   W2[(k0 + 1) * D + d0 + 8]);
            afr[mt][ks][2] = pack_h2(W2[(k0 + 8) * D + d0], W2[(k0 + 9) * D + d0]);
            afr[mt][ks][3] = pack_h2(W2[(k0 + 8) * D + d0 + 8], W2[(k0 + 9) * D + d0 + 8]);
        }
    }
    // d-slot map: i = mt*2 + rh -> d = (2w+mt)*16 + g + rh*8
    int   dsl[4];
    float hb2[4];
#pragma unroll
    for (int i = 0; i < 4; i++) {
        const int mt = i >> 1, rh = i & 1;
        dsl[i] = (2 * w + mt) * 16 + g + rh * 8;
        hb2[i] = 0.5f * b2[dsl[i]];
    }

    // ---- stage h rows ----
    for (int idx = tid; idx < RPC * D; idx += 128)
        sH[idx] = h[(size_t)row0 * D + idx];
    __syncthreads();

    // ---- P[r][k] = b1[k] + sum_d h[r][d]*W1[d][k]  (rows rr, rr+2) ----
    {
        const int kk = tid & 63, rr = tid >> 6;
        float p0 = b1[kk], p1 = p0;
#pragma unroll 4
        for (int d = 0; d < D; d++) {
            const float wv = __ldg(&W1[d * E + kk]);
            p0 = fmaf(sH[rr * D + d],       wv, p0);
            p1 = fmaf(sH[(rr + 2) * D + d], wv, p1);
        }
        sP[rr * E + kk]       = p0;
        sP[(rr + 2) * E + kk] = p1;
    }

    // T-build per-thread constants
    const int kp = lane;
    const int k0 = 2 * kp;
    const float2 w1e0 = *(const float2*)(W1 + 128 * E + k0);
    const float2 w1e1 = *(const float2*)(W1 + 129 * E + k0);
    const float2 w1e2 = *(const float2*)(W1 + 130 * E + k0);
    __syncthreads();

    for (int r = 0; r < RPC; r++) {
        const int row = row0 + r;

        // edge feats -> padded smem (float4 per j)
        const float* efr = ef + (size_t)row * (NJ * 3);
#pragma unroll
        for (int i = 0; i < 6; i++) {
            const int idx = tid + i * 128;
            sE[(idx / 3) * 4 + (idx % 3)] = efr[idx];
        }

        // order-preserving mask compaction
        const unsigned int* adjr = adj + (size_t)row * NJ;
        const int j0 = w * 64 + lane, j1 = w * 64 + 32 + lane;
        const int m0 = (adjr[j0] != 0u), m1 = (adjr[j1] != 0u);
        const unsigned bal0 = __ballot_sync(0xffffffffu, m0);
        const unsigned bal1 = __ballot_sync(0xffffffffu, m1);
        if (lane == 0) sW[w] = __popc(bal0) + __popc(bal1);
        __syncthreads();
        int base = 0;
#pragma unroll
        for (int ww = 0; ww < 4; ww++) if (ww < w) base += sW[ww];
        const int cnt = sW[0] + sW[1] + sW[2] + sW[3];
        const unsigned ltm = (1u << lane) - 1u;
        if (m0) sJ[base + __popc(bal0 & ltm)] = j0;
        if (m1) sJ[base + __popc(bal0) + __popc(bal1 & ltm)] = j1;
        __syncthreads();

        if (cnt > 0) {
            // ---- T build: T[s][k] = relu(P[r][k] + e·W1e), fp16x2 per kp ----
            const float2 P2 = *(const float2*)(sP + r * E + k0);
            for (int s = w; s < cnt; s += 4) {
                const int j = sJ[s];
                const float4 e = *(const float4*)(sE + 4 * j);
                float v0 = fmaf(e.z, w1e2.x, fmaf(e.y, w1e1.x, fmaf(e.x, w1e0.x, P2.x)));
                float v1 = fmaf(e.z, w1e2.y, fmaf(e.y, w1e1.y, fmaf(e.x, w1e0.y, P2.y)));
                *(uint32_t*)(sT + s * PITCH + kp * 4) =
                    pack_h2(fmaxf(v0, 0.f), fmaxf(v1, 0.f));
            }
            __syncthreads();

            // ---- mma over j-tiles of 8 ----
            float sm[4] = {0.f, 0.f, 0.f, 0.f};
            float zx[4] = {-CUDART_INF_F, -CUDART_INF_F, -CUDART_INF_F, -CUDART_INF_F};
            float zn[4] = { CUDART_INF_F,  CUDART_INF_F,  CUDART_INF_F,  CUDART_INF_F};
            const int ntile = (cnt + 7) >> 3;
            const char* sTrow = sT + (size_t)g * PITCH;

            for (int jt = 0; jt < ntile; jt++) {
                float c0[4] = {0.f, 0.f, 0.f, 0.f};
                float c1[4] = {0.f, 0.f, 0.f, 0.f};
                const char* tb = sTrow + jt * (8 * PITCH) + t4 * 4;
#pragma unroll
                for (int ks = 0; ks < 4; ks++) {
                    const uint32_t b0 = *(const uint32_t*)(tb + ks * 32);
                    const uint32_t b1r = *(const uint32_t*)(tb + ks * 32 + 16);
                    mma16816(c0, afr[0][ks], b0, b1r);
                    mma16816(c1, afr[1][ks], b0, b1r);
                }
                const int s0 = jt * 8 + 2 * t4;
#define UPDZ(i, zz) do { const float _z = (zz); \
        sm[i] += sig_half(fmaf(_z, 0.5f, hb2[i])); \
        zx[i] = fmaxf(zx[i], _z); zn[i] = fminf(zn[i], _z); } while (0)
                if (s0 < cnt) {
                    UPDZ(0, c0[0]); UPDZ(1, c0[2]); UPDZ(2, c1[0]); UPDZ(3, c1[2]);
                }
                if (s0 + 1 < cnt) {
                    UPDZ(0, c0[1]); UPDZ(1, c0[3]); UPDZ(2, c1[1]); UPDZ(3, c1[3]);
                }
#undef UPDZ
            }

            // 4-lane (t4 group) reduction
#pragma unroll
            for (int off = 1; off <= 2; off <<= 1) {
#pragma unroll
                for (int i = 0; i < 4; i++) {
                    sm[i] += __shfl_xor_sync(0xffffffffu, sm[i], off);
                    zx[i] = fmaxf(zx[i], __shfl_xor_sync(0xffffffffu, zx[i], off));
                    zn[i] = fminf(zn[i], __shfl_xor_sync(0xffffffffu, zn[i], off));
                }
            }
            if (t4 == 0) {
                const float cntf = (float)cnt;
#pragma unroll
                for (int i = 0; i < 4; i++) {
                    const int d = dsl[i];
                    const float hd = sH[r * D + d];
                    const float cm = hd * sm[i] / cntf;
                    const float gx = sig_half(fmaf(zx[i], 0.5f, hb2[i]));
                    const float gn = sig_half(fmaf(zn[i], 0.5f, hb2[i]));
                    const float cx = (hd >= 0.f) ? hd * gx : hd * gn;
                    g_agg[(size_t)row * (2 * D) + d]     = cm;
                    g_agg[(size_t)row * (2 * D) + D + d] = cx;
                }
            }
        } else {
            g_agg[(size_t)row * (2 * D) + tid]     = 0.f;
            g_agg[(size_t)row * (2 * D) + D + tid] = 0.f;
        }
        __syncthreads();   // protect sE/sJ/sT reuse next row
    }
}

// ---------------------------------------------------------------------------
// Update MLP + residual + LayerNorm — 512 blocks x 512 threads, TR=4 rows,
// 4-way split-k. thread = (d = tid&127, quarter = tid>>7). Partials combine
// in smem. LN finish: warp w (<4) owns row w, pure shuffle reduction.
// ---------------------------------------------------------------------------
__global__ void __launch_bounds__(512)
update_kernel(const float* __restrict__ h,
              const float* __restrict__ U1, const float* __restrict__ b3,
              const float* __restrict__ U2, const float* __restrict__ b4,
              const float* __restrict__ gamma, const float* __restrict__ beta,
              float* __restrict__ out) {
    const int rbase = blockIdx.x * TR;
    const int tid  = threadIdx.x;
    const int d    = tid & 127;
    const int quar = tid >> 7;
    __shared__ __align__(16) float sa[TR][3 * D];     // [h | mean | max]   6KB
    __shared__ __align__(16) float sy[TR][D];         // relu hidden        2KB
    __shared__ __align__(16) float sacc[4][TR][D];    // split-k partials   8KB

    // stage input rows (TR*384 = 1536 elems, 3 iters)
    for (int idx = tid; idx < TR * 3 * D; idx += 512) {
        const int r = idx / (3 * D);
        const int m = idx % (3 * D);
        float v;
        if (m < D) v = h[(rbase + r) * D + m];
        else       v = g_agg[(size_t)(rbase + r) * (2 * D) + (m - D)];
        sa[r][m] = v;
    }
    __syncthreads();

    float acc[TR];
    // ---- GEMM1: y = relu(X @ U1 + b3); this quarter covers 96 k-values ----
    {
        const float init = quar ? 0.f : b3[d];
#pragma unroll
        for (int r = 0; r < TR; r++) acc[r] = init;
    }
    const int m0 = quar * 96;
#pragma unroll 4
    for (int g4 = 0; g4 < 24; g4++) {
        const int m = m0 + g4 * 4;
        const float u0 = U1[(m + 0) * D + d];
        const float u1 = U1[(m + 1) * D + d];
        const float u2 = U1[(m + 2) * D + d];
        const float u3 = U1[(m + 3) * D + d];
#pragma unroll
        for (int r = 0; r < TR; r++) {
            const float4 a4 = *(const float4*)(&sa[r][m]);
            acc[r] = fmaf(a4.x, u0, acc[r]);
            acc[r] = fmaf(a4.y, u1, acc[r]);
            acc[r] = fmaf(a4.z, u2, acc[r]);
            acc[r] = fmaf(a4.w, u3, acc[r]);
        }
    }
#pragma unroll
    for (int r = 0; r < TR; r++) sacc[quar][r][d] = acc[r];
    __syncthreads();

    // combine + relu (TR*D = 512 elems = 1 per thread)
    {
        const int r = tid >> 7, dd = tid & 127;
        sy[r][dd] = fmaxf(sacc[0][r][dd] + sacc[1][r][dd] +
                          sacc[2][r][dd] + sacc[3][r][dd], 0.f);
    }
    __syncthreads();

    // ---- GEMM2: upd = y @ U2 + b4; this quarter covers 32 k-values ----
    {
        const float init = quar ? 0.f : b4[d];
#pragma unroll
        for (int r = 0; r < TR; r++) acc[r] = init;
    }
    const int kk0 = quar * 32;
#pragma unroll 4
    for (int g4 = 0; g4 < 8; g4++) {
        const int k = kk0 + g4 * 4;
        const float u0 = U2[(k + 0) * D + d];
        const float u1 = U2[(k + 1) * D + d];
        const float u2 = U2[(k + 2) * D + d];
        const float u3 = U2[(k + 3) * D + d];
#pragma unroll
        for (int r = 0; r < TR; r++) {
            const float4 y4 = *(const float4*)(&sy[r][k]);
            acc[r] = fmaf(y4.x, u0, acc[r]);
            acc[r] = fmaf(y4.y, u1, acc[r]);
            acc[r] = fmaf(y4.z, u2, acc[r]);
            acc[r] = fmaf(y4.w, u3, acc[r]);
        }
    }
#pragma unroll
    for (int r = 0; r < TR; r++) sacc[quar][r][d] = acc[r];
    __syncthreads();

    // ---- residual + LayerNorm: warp w owns row w (w < TR) ----
    const int w = tid >> 5, lane = tid & 31;
    if (w < TR) {
        float x[4];
        float s = 0.f, q = 0.f;
#pragma unroll
        for (int i = 0; i < 4; i++) {
            const int dd = lane + i * 32;
            x[i] = sa[w][dd] + sacc[0][w][dd] + sacc[1][w][dd] +
                   sacc[2][w][dd] + sacc[3][w][dd];
            s += x[i];
            q = fmaf(x[i], x[i], q);
        }
#pragma unroll
        for (int off = 16; off; off >>= 1) {
            s += __shfl_xor_sync(0xffffffffu, s, off);
            q += __shfl_xor_sync(0xffffffffu, q, off);
        }
        const float mu  = s * (1.f / 128.f);
        const float var = q * (1.f / 128.f) - mu * mu;
        const float inv = rsqrtf(var + 1e-5f);
#pragma unroll
        for (int i = 0; i < 4; i++) {
            const int dd = lane + i * 32;
            out[(rbase + w) * D + dd] = (x[i] - mu) * inv * gamma[dd] + beta[dd];
        }
    }
}

// ---------------------------------------------------------------------------
extern "C" void kernel_launch(void* const* d_in, const int* in_sizes, int n_in,
                              void* d_out, int out_size) {
    const float*        h     = (const float*)d_in[0];
    const float*        ef    = (const float*)d_in[1];
    const unsigned int* adj   = (const unsigned int*)d_in[2];
    const float*        W1    = (const float*)d_in[3];
    const float*        b1    = (const float*)d_in[4];
    const float*        W2    = (const float*)d_in[5];
    const float*        b2    = (const float*)d_in[6];
    const float*        U1    = (const float*)d_in[7];
    const float*        b3    = (const float*)d_in[8];
    const float*        U2    = (const float*)d_in[9];
    const float*        b4    = (const float*)d_in[10];
    const float*        gamma = (const float*)d_in[11];
    const float*        beta  = (const float*)d_in[12];
    float* out = (float*)d_out;

    gate_kernel<<<ROWS / RPC, 128>>>(h, ef, adj, W1, b1, W2, b2);
    update_kernel<<<ROWS / TR, 512>>>(h, U1, b3, U2, b4, gamma, beta, out);
}

// round 12
// speedup vs baseline: 3.3261x; 1.0284x over previous
#include <cuda_runtime.h>
#include <cuda_fp16.h>
#include <math_constants.h>
#include <cstdint>

// Problem constants
#define ROWS 2048     // B*N
#define D    128
#define E    64
#define NJ   256
#define RPC  4        // rows per CTA in gate kernel
#define TR   4        // rows per block in update kernel (4-way split-k, 512 thr)
#define PITCH 144     // sT row pitch in bytes (128B data + 16B skew)

__device__ float g_agg[ROWS * 2 * D];   // per row: [agg_mean(128) | agg_max(128)]

__device__ __forceinline__ uint32_t pack_h2(float a, float b) {
    __half2 h = __floats2half2_rn(a, b);
    return *(uint32_t*)&h;
}

// D = A(16x16) * B(16x8) + D, fp16 in / fp32 acc. Emits HMMA.16816 on sm_103.
__device__ __forceinline__ void mma16816(float c[4], const uint32_t a[4],
                                         uint32_t b0, uint32_t b1) {
    asm volatile(
        "mma.sync.aligned.m16n8k16.row.col.f32.f16.f16.f32 "
        "{%0,%1,%2,%3}, {%4,%5,%6,%7}, {%8,%9}, {%0,%1,%2,%3};"
        : "+f"(c[0]), "+f"(c[1]), "+f"(c[2]), "+f"(c[3])
        : "r"(a[0]), "r"(a[1]), "r"(a[2]), "r"(a[3]), "r"(b0), "r"(b1));
}

// sigmoid(z + b2) given ha = 0.5*z + 0.5*b2   (1 MUFU)
__device__ __forceinline__ float sig_half(float ha) {
    float t;
    asm("tanh.approx.f32 %0, %1;" : "=f"(t) : "f"(ha));
    return fmaf(t, 0.5f, 0.5f);
}

__device__ __forceinline__ float tanh_ap(float x) {
    float t;
    asm("tanh.approx.f32 %0, %1;" : "=f"(t) : "f"(x));
    return t;
}

// ---------------------------------------------------------------------------
// Gate kernel: 256 threads (8 warps), RPC=4 rows/CTA. Warp w owns d-tile
// [16w, 16w+16). Per row: one-ballot-per-warp compaction; T build spread over
// 8 warps; per-warp 4xHMMA per j-tile; epilogue accumulates sum(tanh), max z,
// min z (thread-local over j), 4-lane shuffle finish.
// ---------------------------------------------------------------------------
__global__ void __launch_bounds__(256)
gate_kernel(const float* __restrict__ h, const float* __restrict__ ef,
            const unsigned int* __restrict__ adj,
            const float* __restrict__ W1, const float* __restrict__ b1,
            const float* __restrict__ W2, const float* __restrict__ b2) {
    __shared__ __align__(16) char  sT[NJ * PITCH];   // fp16 T tile, skewed rows
    __shared__ __align__(16) float sE[NJ * 4];       // edge feats, float4/row
    __shared__ float sH[RPC * D];
    __shared__ float sP[RPC * E];
    __shared__ int   sJ[NJ];
    __shared__ int   sW[8];

    const int tid  = threadIdx.x;
    const int w    = tid >> 5;
    const int lane = tid & 31;
    const int g    = lane >> 2;      // groupID (= n within 8-tile, = m row base)
    const int t4   = lane & 3;       // thread-in-group (= k pair / n pair)
    const int row0 = blockIdx.x * RPC;

    // ---- A fragments: A[d][k] = W2[k][d], ONE m-tile per warp, 4 k-steps ----
    uint32_t afr[4][4];
    {
        const int d0 = w * 16 + g;
#pragma unroll
        for (int ks = 0; ks < 4; ks++) {
            const int k0 = ks * 16 + 2 * t4;
            afr[ks][0] = pack_h2(W2[k0 * D + d0],       W2[(k0 + 1) * D + d0]);
            afr[ks][1] = pack_h2(W2[k0 * D + d0 + 8],   W2[(k0 + 1) * D + d0 + 8]);
            afr[ks][2] = pack_h2(W2[(k0 + 8) * D + d0], W2[(k0 + 9) * D + d0]);
            afr[ks][3] = pack_h2(W2[(k0 + 8) * D + d0 + 8], W2[(k0 + 9) * D + d0 + 8]);
        }
    }
    // d-slot map: i = rh -> d = 16w + g + 8*rh
    int   dsl[2];
    float hb2[2];
#pragma unroll
    for (int i = 0; i < 2; i++) {
        dsl[i] = w * 16 + g + i * 8;
        hb2[i] = 0.5f * b2[dsl[i]];
    }

    // ---- stage h rows (512 floats, 2 iters) ----
#pragma unroll
    for (int i = 0; i < 2; i++)
        sH[tid + i * 256] = h[(size_t)row0 * D + tid + i * 256];
    __syncthreads();

    // ---- P[r][k] = b1[k] + sum_d h[r][d]*W1[d][k]; thread = (k, row) ----
    {
        const int kk = tid & 63, rr = tid >> 6;
        float p0 = b1[kk];
#pragma unroll 4
        for (int d = 0; d < D; d++)
            p0 = fmaf(sH[rr * D + d], __ldg(&W1[d * E + kk]), p0);
        sP[rr * E + kk] = p0;
    }

    // T-build per-thread constants (k-pair = lane)
    const int kp = lane;
    const int k0 = 2 * kp;
    const float2 w1e0 = *(const float2*)(W1 + 128 * E + k0);
    const float2 w1e1 = *(const float2*)(W1 + 129 * E + k0);
    const float2 w1e2 = *(const float2*)(W1 + 130 * E + k0);
    __syncthreads();

    for (int r = 0; r < RPC; r++) {
        const int row = row0 + r;

        // edge feats -> padded smem (float4 per j), 768 floats in 3 iters
        const float* efr = ef + (size_t)row * (NJ * 3);
#pragma unroll
        for (int i = 0; i < 3; i++) {
            const int idx = tid + i * 256;
            sE[(idx / 3) * 4 + (idx % 3)] = efr[idx];
        }

        // order-preserving mask compaction: warp w covers j in [32w, 32w+32)
        const unsigned int* adjr = adj + (size_t)row * NJ;
        const int j0 = w * 32 + lane;
        const int m0 = (adjr[j0] != 0u);
        const unsigned bal = __ballot_sync(0xffffffffu, m0);
        if (lane == 0) sW[w] = __popc(bal);
        __syncthreads();
        int base = 0;
        int cnt = 0;
#pragma unroll
        for (int ww = 0; ww < 8; ww++) {
            if (ww < w) base += sW[ww];
            cnt += sW[ww];
        }
        if (m0) sJ[base + __popc(bal & ((1u << lane) - 1u))] = j0;
        __syncthreads();

        if (cnt > 0) {
            // ---- T build: T[s][k] = relu(P[r][k] + e·W1e), fp16x2 per kp ----
            const float2 P2 = *(const float2*)(sP + r * E + k0);
            for (int s = w; s < cnt; s += 8) {
                const int j = sJ[s];
                const float4 e = *(const float4*)(sE + 4 * j);
                float v0 = fmaf(e.z, w1e2.x, fmaf(e.y, w1e1.x, fmaf(e.x, w1e0.x, P2.x)));
                float v1 = fmaf(e.z, w1e2.y, fmaf(e.y, w1e1.y, fmaf(e.x, w1e0.y, P2.y)));
                *(uint32_t*)(sT + s * PITCH + kp * 4) =
                    pack_h2(fmaxf(v0, 0.f), fmaxf(v1, 0.f));
            }
            __syncthreads();

            // ---- mma over j-tiles of 8 (4 HMMA per tile, one m-tile) ----
            float st[2] = {0.f, 0.f};                          // sum of tanh
            float zx[2] = {-CUDART_INF_F, -CUDART_INF_F};
            float zn[2] = { CUDART_INF_F,  CUDART_INF_F};
            const int ntile = (cnt + 7) >> 3;
            const char* sTrow = sT + (size_t)g * PITCH;

            for (int jt = 0; jt < ntile; jt++) {
                float c0[4] = {0.f, 0.f, 0.f, 0.f};
                const char* tb = sTrow + jt * (8 * PITCH) + t4 * 4;
#pragma unroll
                for (int ks = 0; ks < 4; ks++) {
                    const uint32_t b0 = *(const uint32_t*)(tb + ks * 32);
                    const uint32_t b1r = *(const uint32_t*)(tb + ks * 32 + 16);
                    mma16816(c0, afr[ks], b0, b1r);
                }
                const int s0 = jt * 8 + 2 * t4;
#define UPDZ(i, zz) do { const float _z = (zz); \
        st[i] += tanh_ap(fmaf(_z, 0.5f, hb2[i])); \
        zx[i] = fmaxf(zx[i], _z); zn[i] = fminf(zn[i], _z); } while (0)
                if (s0 < cnt)     { UPDZ(0, c0[0]); UPDZ(1, c0[2]); }
                if (s0 + 1 < cnt) { UPDZ(0, c0[1]); UPDZ(1, c0[3]); }
#undef UPDZ
            }

            // 4-lane (t4 group) reduction
#pragma unroll
            for (int off = 1; off <= 2; off <<= 1) {
#pragma unroll
                for (int i = 0; i < 2; i++) {
                    st[i] += __shfl_xor_sync(0xffffffffu, st[i], off);
                    zx[i] = fmaxf(zx[i], __shfl_xor_sync(0xffffffffu, zx[i], off));
                    zn[i] = fminf(zn[i], __shfl_xor_sync(0xffffffffu, zn[i], off));
                }
            }
            if (t4 == 0) {
                const float cntf = (float)cnt;
#pragma unroll
                for (int i = 0; i < 2; i++) {
                    const int d = dsl[i];
                    const float hd = sH[r * D + d];
                    // sum sigma = 0.5*sum tanh + 0.5*cnt
                    const float sumg = fmaf(0.5f, st[i], 0.5f * cntf);
                    const float cm = hd * sumg / cntf;
                    const float gx = sig_half(fmaf(zx[i], 0.5f, hb2[i]));
                    const float gn = sig_half(fmaf(zn[i], 0.5f, hb2[i]));
                    const float cx = (hd >= 0.f) ? hd * gx : hd * gn;
                    g_agg[(size_t)row * (2 * D) + d]     = cm;
                    g_agg[(size_t)row * (2 * D) + D + d] = cx;
                }
            }
        } else {
            if (tid < D) {
                g_agg[(size_t)row * (2 * D) + tid]     = 0.f;
                g_agg[(size_t)row * (2 * D) + D + tid] = 0.f;
            }
        }
        __syncthreads();   // protect sE/sJ/sT reuse next row
    }
}

// ---------------------------------------------------------------------------
// Update MLP + residual + LayerNorm — unchanged from R11 (validated).
// 512 blocks x 512 threads, TR=4 rows, 4-way split-k.
// ---------------------------------------------------------------------------
__global__ void __launch_bounds__(512)
update_kernel(const float* __restrict__ h,
              const float* __restrict__ U1, const float* __restrict__ b3,
              const float* __restrict__ U2, const float* __restrict__ b4,
              const float* __restrict__ gamma, const float* __restrict__ beta,
              float* __restrict__ out) {
    const int rbase = blockIdx.x * TR;
    const int tid  = threadIdx.x;
    const int d    = tid & 127;
    const int quar = tid >> 7;
    __shared__ __align__(16) float sa[TR][3 * D];     // [h | mean | max]   6KB
    __shared__ __align__(16) float sy[TR][D];         // relu hidden        2KB
    __shared__ __align__(16) float sacc[4][TR][D];    // split-k partials   8KB

    for (int idx = tid; idx < TR * 3 * D; idx += 512) {
        const int r = idx / (3 * D);
        const int m = idx % (3 * D);
        float v;
        if (m < D) v = h[(rbase + r) * D + m];
        else       v = g_agg[(size_t)(rbase + r) * (2 * D) + (m - D)];
        sa[r][m] = v;
    }
    __syncthreads();

    float acc[TR];
    // ---- GEMM1: y = relu(X @ U1 + b3); this quarter covers 96 k-values ----
    {
        const float init = quar ? 0.f : b3[d];
#pragma unroll
        for (int r = 0; r < TR; r++) acc[r] = init;
    }
    const int m0 = quar * 96;
#pragma unroll 4
    for (int g4 = 0; g4 < 24; g4++) {
        const int m = m0 + g4 * 4;
        const float u0 = U1[(m + 0) * D + d];
        const float u1 = U1[(m + 1) * D + d];
        const float u2 = U1[(m + 2) * D + d];
        const float u3 = U1[(m + 3) * D + d];
#pragma unroll
        for (int r = 0; r < TR; r++) {
            const float4 a4 = *(const float4*)(&sa[r][m]);
            acc[r] = fmaf(a4.x, u0, acc[r]);
            acc[r] = fmaf(a4.y, u1, acc[r]);
            acc[r] = fmaf(a4.z, u2, acc[r]);
            acc[r] = fmaf(a4.w, u3, acc[r]);
        }
    }
#pragma unroll
    for (int r = 0; r < TR; r++) sacc[quar][r][d] = acc[r];
    __syncthreads();

    // combine + relu (TR*D = 512 elems = 1 per thread)
    {
        const int r = tid >> 7, dd = tid & 127;
        sy[r][dd] = fmaxf(sacc[0][r][dd] + sacc[1][r][dd] +
                          sacc[2][r][dd] + sacc[3][r][dd], 0.f);
    }
    __syncthreads();

    // ---- GEMM2: upd = y @ U2 + b4; this quarter covers 32 k-values ----
    {
        const float init = quar ? 0.f : b4[d];
#pragma unroll
        for (int r = 0; r < TR; r++) acc[r] = init;
    }
    const int kk0 = quar * 32;
#pragma unroll 4
    for (int g4 = 0; g4 < 8; g4++) {
        const int k = kk0 + g4 * 4;
        const float u0 = U2[(k + 0) * D + d];
        const float u1 = U2[(k + 1) * D + d];
        const float u2 = U2[(k + 2) * D + d];
        const float u3 = U2[(k + 3) * D + d];
#pragma unroll
        for (int r = 0; r < TR; r++) {
            const float4 y4 = *(const float4*)(&sy[r][k]);
            acc[r] = fmaf(y4.x, u0, acc[r]);
            acc[r] = fmaf(y4.y, u1, acc[r]);
            acc[r] = fmaf(y4.z, u2, acc[r]);
            acc[r] = fmaf(y4.w, u3, acc[r]);
        }
    }
#pragma unroll
    for (int r = 0; r < TR; r++) sacc[quar][r][d] = acc[r];
    __syncthreads();

    // ---- residual + LayerNorm: warp w owns row w (w < TR) ----
    const int w = tid >> 5, lane = tid & 31;
    if (w < TR) {
        float x[4];
        float s = 0.f, q = 0.f;
#pragma unroll
        for (int i = 0; i < 4; i++) {
            const int dd = lane + i * 32;
            x[i] = sa[w][dd] + sacc[0][w][dd] + sacc[1][w][dd] +
                   sacc[2][w][dd] + sacc[3][w][dd];
            s += x[i];
            q = fmaf(x[i], x[i], q);
        }
#pragma unroll
        for (int off = 16; off; off >>= 1) {
            s += __shfl_xor_sync(0xffffffffu, s, off);
            q += __shfl_xor_sync(0xffffffffu, q, off);
        }
        const float mu  = s * (1.f / 128.f);
        const float var = q * (1.f / 128.f) - mu * mu;
        const float inv = rsqrtf(var + 1e-5f);
#pragma unroll
        for (int i = 0; i < 4; i++) {
            const int dd = lane + i * 32;
            out[(rbase + w) * D + dd] = (x[i] - mu) * inv * gamma[dd] + beta[dd];
        }
    }
}

// ---------------------------------------------------------------------------
extern "C" void kernel_launch(void* const* d_in, const int* in_sizes, int n_in,
                              void* d_out, int out_size) {
    const float*        h     = (const float*)d_in[0];
    const float*        ef    = (const float*)d_in[1];
    const unsigned int* adj   = (const unsigned int*)d_in[2];
    const float*        W1    = (const float*)d_in[3];
    const float*        b1    = (const float*)d_in[4];
    const float*        W2    = (const float*)d_in[5];
    const float*        b2    = (const float*)d_in[6];
    const float*        U1    = (const float*)d_in[7];
    const float*        b3    = (const float*)d_in[8];
    const float*        U2    = (const float*)d_in[9];
    const float*        b4    = (const float*)d_in[10];
    const float*        gamma = (const float*)d_in[11];
    const float*        beta  = (const float*)d_in[12];
    float* out = (float*)d_out;

    gate_kernel<<<ROWS / RPC, 256>>>(h, ef, adj, W1, b1, W2, b2);
    update_kernel<<<ROWS / TR, 512>>>(h, U1, b3, U2, b4, gamma, beta, out);
}

// round 13
// speedup vs baseline: 3.5263x; 1.0602x over previous
#include <cuda_runtime.h>
#include <cuda_fp16.h>
#include <math_constants.h>
#include <cstdint>

// Problem constants
#define ROWS 2048     // B*N
#define D    128
#define E    64
#define NJ   256
#define TR   4        // rows per block in update kernel (4-way split-k, 512 thr)
#define PITCH 144     // sT row pitch in bytes (128B data + 16B skew)

__device__ float g_agg[ROWS * 2 * D];   // per row: [agg_mean(128) | agg_max(128)]

__device__ __forceinline__ uint32_t pack_h2(float a, float b) {
    __half2 h = __floats2half2_rn(a, b);
    return *(uint32_t*)&h;
}

// D = A(16x16) * B(16x8) + D, fp16 in / fp32 acc. Emits HMMA.16816 on sm_103.
__device__ __forceinline__ void mma16816(float c[4], const uint32_t a[4],
                                         uint32_t b0, uint32_t b1) {
    asm volatile(
        "mma.sync.aligned.m16n8k16.row.col.f32.f16.f16.f32 "
        "{%0,%1,%2,%3}, {%4,%5,%6,%7}, {%8,%9}, {%0,%1,%2,%3};"
        : "+f"(c[0]), "+f"(c[1]), "+f"(c[2]), "+f"(c[3])
        : "r"(a[0]), "r"(a[1]), "r"(a[2]), "r"(a[3]), "r"(b0), "r"(b1));
}

// sigmoid(z + b2) given ha = 0.5*z + 0.5*b2   (1 MUFU)
__device__ __forceinline__ float sig_half(float ha) {
    float t;
    asm("tanh.approx.f32 %0, %1;" : "=f"(t) : "f"(ha));
    return fmaf(t, 0.5f, 0.5f);
}

__device__ __forceinline__ float tanh_ap(float x) {
    float t;
    asm("tanh.approx.f32 %0, %1;" : "=f"(t) : "f"(x));
    return t;
}

// ---------------------------------------------------------------------------
// Gate kernel: ONE row per CTA (grid=2048), 256 threads (8 warps).
// All DRAM loads issued up front; P-build split 4 ways to shorten the chain;
// warp w owns d-tile [16w,16w+16); epilogue thread-local over j.
// ---------------------------------------------------------------------------
__global__ void __launch_bounds__(256)
gate_kernel(const float* __restrict__ h, const float* __restrict__ ef,
            const unsigned int* __restrict__ adj,
            const float* __restrict__ W1, const float* __restrict__ b1,
            const float* __restrict__ W2, const float* __restrict__ b2) {
    __shared__ __align__(16) char  sT[NJ * PITCH];   // fp16 T tile, skewed rows
    __shared__ __align__(16) float sE[NJ * 4];       // edge feats, float4/row
    __shared__ float sH[D];
    __shared__ float sPp[4][E];                      // P partials
    __shared__ float sP[E];
    __shared__ int   sJ[NJ];
    __shared__ int   sW[8];

    const int tid  = threadIdx.x;
    const int w    = tid >> 5;
    const int lane = tid & 31;
    const int g    = lane >> 2;      // groupID
    const int t4   = lane & 3;       // thread-in-group
    const int row  = blockIdx.x;

    // ---- issue ALL dram loads up front (overlap with compute below) ----
    const float* efr = ef + (size_t)row * (NJ * 3);
    const float e0 = efr[tid];
    const float e1 = efr[tid + 256];
    const float e2 = efr[tid + 512];
    const int   m0 = (adj[(size_t)row * NJ + tid] != 0u);
    if (tid < D) sH[tid] = h[(size_t)row * D + tid];

    // ballot per warp (j = tid exactly covers 0..255)
    const unsigned bal = __ballot_sync(0xffffffffu, m0);
    if (lane == 0) sW[w] = __popc(bal);

    // ---- A fragments: A[d][k] = W2[k][d], one m-tile per warp (L1/L2 hot) ----
    uint32_t afr[4][4];
    {
        const int d0 = w * 16 + g;
#pragma unroll
        for (int ks = 0; ks < 4; ks++) {
            const int k0 = ks * 16 + 2 * t4;
            afr[ks][0] = pack_h2(W2[k0 * D + d0],       W2[(k0 + 1) * D + d0]);
            afr[ks][1] = pack_h2(W2[k0 * D + d0 + 8],   W2[(k0 + 1) * D + d0 + 8]);
            afr[ks][2] = pack_h2(W2[(k0 + 8) * D + d0], W2[(k0 + 9) * D + d0]);
            afr[ks][3] = pack_h2(W2[(k0 + 8) * D + d0 + 8], W2[(k0 + 9) * D + d0 + 8]);
        }
    }
    int   dsl[2];
    float hb2[2];
#pragma unroll
    for (int i = 0; i < 2; i++) {
        dsl[i] = w * 16 + g + i * 8;
        hb2[i] = 0.5f * b2[dsl[i]];
    }

    // ---- stash ef into padded smem (pre-sync writes, post-sync reads) ----
    sE[(tid / 3) * 4 + (tid % 3)]                 = e0;
    sE[((tid + 256) / 3) * 4 + ((tid + 256) % 3)] = e1;
    sE[((tid + 512) / 3) * 4 + ((tid + 512) % 3)] = e2;

    // T-build constants (k-pair = lane)
    const int k0p = 2 * lane;
    const float2 w1e0 = *(const float2*)(W1 + 128 * E + k0p);
    const float2 w1e1 = *(const float2*)(W1 + 129 * E + k0p);
    const float2 w1e2 = *(const float2*)(W1 + 130 * E + k0p);

    __syncthreads();   // sH, sW ready

    // ---- P partials: thread (kk, part) does 32-d slice ----
    {
        const int kk = tid & 63, part = tid >> 6;
        const int db = part * 32;
        float p = 0.f;
#pragma unroll 8
        for (int d = 0; d < 32; d++)
            p = fmaf(sH[db + d], __ldg(&W1[(db + d) * E + kk]), p);
        sPp[part][kk] = p;
    }

    // ---- order-preserving compaction (needs sW) ----
    int base = 0, cnt = 0;
#pragma unroll
    for (int ww = 0; ww < 8; ww++) {
        if (ww < w) base += sW[ww];
        cnt += sW[ww];
    }
    if (m0) sJ[base + __popc(bal & ((1u << lane) - 1u))] = tid;
    __syncthreads();   // sPp, sJ ready

    if (tid < E)
        sP[tid] = b1[tid] + ((sPp[0][tid] + sPp[1][tid]) +
                             (sPp[2][tid] + sPp[3][tid]));
    __syncthreads();   // sP ready (sE was ready at first sync)

    if (cnt == 0) {
        if (tid < D) {
            g_agg[(size_t)row * (2 * D) + tid]     = 0.f;
            g_agg[(size_t)row * (2 * D) + D + tid] = 0.f;
        }
        return;
    }

    // ---- T build: T[s][k] = relu(P[k] + e·W1e), fp16x2 per lane ----
    {
        const float2 P2 = *(const float2*)(sP + k0p);
        for (int s = w; s < cnt; s += 8) {
            const int j = sJ[s];
            const float4 e = *(const float4*)(sE + 4 * j);
            float v0 = fmaf(e.z, w1e2.x, fmaf(e.y, w1e1.x, fmaf(e.x, w1e0.x, P2.x)));
            float v1 = fmaf(e.z, w1e2.y, fmaf(e.y, w1e1.y, fmaf(e.x, w1e0.y, P2.y)));
            *(uint32_t*)(sT + s * PITCH + lane * 4) =
                pack_h2(fmaxf(v0, 0.f), fmaxf(v1, 0.f));
        }
    }
    __syncthreads();   // sT ready

    // ---- mma over j-tiles of 8 (4 HMMA per tile) ----
    float st[2] = {0.f, 0.f};                          // sum of tanh
    float zx[2] = {-CUDART_INF_F, -CUDART_INF_F};
    float zn[2] = { CUDART_INF_F,  CUDART_INF_F};
    const int ntile = (cnt + 7) >> 3;
    const char* sTrow = sT + (size_t)g * PITCH;

    for (int jt = 0; jt < ntile; jt++) {
        float c0[4] = {0.f, 0.f, 0.f, 0.f};
        const char* tb = sTrow + jt * (8 * PITCH) + t4 * 4;
#pragma unroll
        for (int ks = 0; ks < 4; ks++) {
            const uint32_t b0 = *(const uint32_t*)(tb + ks * 32);
            const uint32_t b1r = *(const uint32_t*)(tb + ks * 32 + 16);
            mma16816(c0, afr[ks], b0, b1r);
        }
        const int s0 = jt * 8 + 2 * t4;
#define UPDZ(i, zz) do { const float _z = (zz); \
    st[i] += tanh_ap(fmaf(_z, 0.5f, hb2[i])); \
    zx[i] = fmaxf(zx[i], _z); zn[i] = fminf(zn[i], _z); } while (0)
        if (s0 < cnt)     { UPDZ(0, c0[0]); UPDZ(1, c0[2]); }
        if (s0 + 1 < cnt) { UPDZ(0, c0[1]); UPDZ(1, c0[3]); }
#undef UPDZ
    }

    // 4-lane (t4 group) reduction
#pragma unroll
    for (int off = 1; off <= 2; off <<= 1) {
#pragma unroll
        for (int i = 0; i < 2; i++) {
            st[i] += __shfl_xor_sync(0xffffffffu, st[i], off);
            zx[i] = fmaxf(zx[i], __shfl_xor_sync(0xffffffffu, zx[i], off));
            zn[i] = fminf(zn[i], __shfl_xor_sync(0xffffffffu, zn[i], off));
        }
    }
    if (t4 == 0) {
        const float cntf = (float)cnt;
#pragma unroll
        for (int i = 0; i < 2; i++) {
            const int d = dsl[i];
            const float hd = sH[d];
            const float sumg = fmaf(0.5f, st[i], 0.5f * cntf); // Σσ = ½Σtanh + ½cnt
            const float cm = hd * sumg / cntf;
            const float gx = sig_half(fmaf(zx[i], 0.5f, hb2[i]));
            const float gn = sig_half(fmaf(zn[i], 0.5f, hb2[i]));
            const float cx = (hd >= 0.f) ? hd * gx : hd * gn;
            g_agg[(size_t)row * (2 * D) + d]     = cm;
            g_agg[(size_t)row * (2 * D) + D + d] = cx;
        }
    }
}

// ---------------------------------------------------------------------------
// Update MLP + residual + LayerNorm — unchanged from R12 (validated).
// 512 blocks x 512 threads, TR=4 rows, 4-way split-k.
// ---------------------------------------------------------------------------
__global__ void __launch_bounds__(512)
update_kernel(const float* __restrict__ h,
              const float* __restrict__ U1, const float* __restrict__ b3,
              const float* __restrict__ U2, const float* __restrict__ b4,
              const float* __restrict__ gamma, const float* __restrict__ beta,
              float* __restrict__ out) {
    const int rbase = blockIdx.x * TR;
    const int tid  = threadIdx.x;
    const int d    = tid & 127;
    const int quar = tid >> 7;
    __shared__ __align__(16) float sa[TR][3 * D];     // [h | mean | max]   6KB
    __shared__ __align__(16) float sy[TR][D];         // relu hidden        2KB
    __shared__ __align__(16) float sacc[4][TR][D];    // split-k partials   8KB

    for (int idx = tid; idx < TR * 3 * D; idx += 512) {
        const int r = idx / (3 * D);
        const int m = idx % (3 * D);
        float v;
        if (m < D) v = h[(rbase + r) * D + m];
        else       v = g_agg[(size_t)(rbase + r) * (2 * D) + (m - D)];
        sa[r][m] = v;
    }
    __syncthreads();

    float acc[TR];
    // ---- GEMM1: y = relu(X @ U1 + b3); this quarter covers 96 k-values ----
    {
        const float init = quar ? 0.f : b3[d];
#pragma unroll
        for (int r = 0; r < TR; r++) acc[r] = init;
    }
    const int m0 = quar * 96;
#pragma unroll 4
    for (int g4 = 0; g4 < 24; g4++) {
        const int m = m0 + g4 * 4;
        const float u0 = U1[(m + 0) * D + d];
        const float u1 = U1[(m + 1) * D + d];
        const float u2 = U1[(m + 2) * D + d];
        const float u3 = U1[(m + 3) * D + d];
#pragma unroll
        for (int r = 0; r < TR; r++) {
            const float4 a4 = *(const float4*)(&sa[r][m]);
            acc[r] = fmaf(a4.x, u0, acc[r]);
            acc[r] = fmaf(a4.y, u1, acc[r]);
            acc[r] = fmaf(a4.z, u2, acc[r]);
            acc[r] = fmaf(a4.w, u3, acc[r]);
        }
    }
#pragma unroll
    for (int r = 0; r < TR; r++) sacc[quar][r][d] = acc[r];
    __syncthreads();

    // combine + relu (TR*D = 512 elems = 1 per thread)
    {
        const int r = tid >> 7, dd = tid & 127;
        sy[r][dd] = fmaxf(sacc[0][r][dd] + sacc[1][r][dd] +
                          sacc[2][r][dd] + sacc[3][r][dd], 0.f);
    }
    __syncthreads();

    // ---- GEMM2: upd = y @ U2 + b4; this quarter covers 32 k-values ----
    {
        const float init = quar ? 0.f : b4[d];
#pragma unroll
        for (int r = 0; r < TR; r++) acc[r] = init;
    }
    const int kk0 = quar * 32;
#pragma unroll 4
    for (int g4 = 0; g4 < 8; g4++) {
        const int k = kk0 + g4 * 4;
        const float u0 = U2[(k + 0) * D + d];
        const float u1 = U2[(k + 1) * D + d];
        const float u2 = U2[(k + 2) * D + d];
        const float u3 = U2[(k + 3) * D + d];
#pragma unroll
        for (int r = 0; r < TR; r++) {
            const float4 y4 = *(const float4*)(&sy[r][k]);
            acc[r] = fmaf(y4.x, u0, acc[r]);
            acc[r] = fmaf(y4.y, u1, acc[r]);
            acc[r] = fmaf(y4.z, u2, acc[r]);
            acc[r] = fmaf(y4.w, u3, acc[r]);
        }
    }
#pragma unroll
    for (int r = 0; r < TR; r++) sacc[quar][r][d] = acc[r];
    __syncthreads();

    // ---- residual + LayerNorm: warp w owns row w (w < TR) ----
    const int w = tid >> 5, lane = tid & 31;
    if (w < TR) {
        float x[4];
        float s = 0.f, q = 0.f;
#pragma unroll
        for (int i = 0; i < 4; i++) {
            const int dd = lane + i * 32;
            x[i] = sa[w][dd] + sacc[0][w][dd] + sacc[1][w][dd] +
                   sacc[2][w][dd] + sacc[3][w][dd];
            s += x[i];
            q = fmaf(x[i], x[i], q);
        }
#pragma unroll
        for (int off = 16; off; off >>= 1) {
            s += __shfl_xor_sync(0xffffffffu, s, off);
            q += __shfl_xor_sync(0xffffffffu, q, off);
        }
        const float mu  = s * (1.f / 128.f);
        const float var = q * (1.f / 128.f) - mu * mu;
        const float inv = rsqrtf(var + 1e-5f);
#pragma unroll
        for (int i = 0; i < 4; i++) {
            const int dd = lane + i * 32;
            out[(rbase + w) * D + dd] = (x[i] - mu) * inv * gamma[dd] + beta[dd];
        }
    }
}

// ---------------------------------------------------------------------------
extern "C" void kernel_launch(void* const* d_in, const int* in_sizes, int n_in,
                              void* d_out, int out_size) {
    const float*        h     = (const float*)d_in[0];
    const float*        ef    = (const float*)d_in[1];
    const unsigned int* adj   = (const unsigned int*)d_in[2];
    const float*        W1    = (const float*)d_in[3];
    const float*        b1    = (const float*)d_in[4];
    const float*        W2    = (const float*)d_in[5];
    const float*        b2    = (const float*)d_in[6];
    const float*        U1    = (const float*)d_in[7];
    const float*        b3    = (const float*)d_in[8];
    const float*        U2    = (const float*)d_in[9];
    const float*        b4    = (const float*)d_in[10];
    const float*        gamma = (const float*)d_in[11];
    const float*        beta  = (const float*)d_in[12];
    float* out = (float*)d_out;

    gate_kernel<<<ROWS, 256>>>(h, ef, adj, W1, b1, W2, b2);
    update_kernel<<<ROWS / TR, 512>>>(h, U1, b3, U2, b4, gamma, beta, out);
}